// round 14
// baseline (speedup 1.0000x reference)
#include <cuda_runtime.h>
#include <math.h>

#define BB 32
#define HH 16
#define KVN 8192
#define DHD 64
#define DM 1024
#define SPLITS 8
#define WARPS_PER_BLK 8
#define ROWS_PER_WARP (KVN / (SPLITS * WARPS_PER_BLK))   /* 128 */
#define NPART SPLITS                                      /* 8 partials per (b,h) */
#define IC_QKV 16                                         /* 64-row i-chunks */
#define IC_PROJ 32                                        /* 32-row i-chunks */

__device__ float g_qkv_part[IC_QKV * BB * 3 * DM];         /* 6.3 MB */
__device__ float g_proj_part[IC_PROJ * BB * DM];           /* 4.2 MB */
__device__ float g_pl[BB * HH * NPART];
__device__ float g_pacc[(size_t)BB * HH * NPART * DHD];    /* 1 MB */
__device__ float g_ctx[BB * DM];
__device__ unsigned int g_done[BB * HH];                   /* zero-init; self-resetting */

/* ============ Batched QKV GEMV: weight read ONCE, reused across all 32 b ======= */
/* grid (24 j-tiles, 16 i-chunks of 64 rows), 128 threads. */
__global__ void qkv_part_kernel(const float* __restrict__ x,
                                const float* __restrict__ w) {
    __shared__ float xs[64 * 33];
    const int tid = threadIdx.x;
    const int j = blockIdx.x * 128 + tid;
    const int i0 = blockIdx.y * 64;

    for (int idx = tid; idx < BB * 64; idx += 128) {
        const int bb = idx >> 6, ii = idx & 63;
        xs[ii * 33 + bb] = x[bb * DM + i0 + ii];
    }
    __syncthreads();

    float acc[BB];
    #pragma unroll
    for (int bb = 0; bb < BB; bb++) acc[bb] = 0.f;

    const float* wp = w + (size_t)i0 * (3 * DM) + j;
    #pragma unroll 4
    for (int i = 0; i < 64; i++) {
        const float wv = wp[(size_t)i * (3 * DM)];
        #pragma unroll
        for (int bb = 0; bb < BB; bb++) acc[bb] += xs[i * 33 + bb] * wv;
    }

    float* op = g_qkv_part + (size_t)blockIdx.y * BB * 3 * DM + j;
    #pragma unroll
    for (int bb = 0; bb < BB; bb++) op[(size_t)bb * 3 * DM] = acc[bb];
}

/* ---------------- Fused attention: q-reduce prologue + stream + combine --------- */
/* grid (SPLITS, H, B), 256 thr. No max tracking (scores bounded, fp32-safe;       */
/* softmax shift-invariant). Last block per (b,h) combines partials + current tok. */
__global__ void __launch_bounds__(256) attn_kernel(const float* __restrict__ Kc,
                                                   const float* __restrict__ Vc,
                                                   const float* __restrict__ ba) {
    const int split = blockIdx.x, h = blockIdx.y, b = blockIdx.z;
    const int warp = threadIdx.x >> 5, lane = threadIdx.x & 31;
    const int half = lane >> 4, li = lane & 15;
    const int bh = b * HH + h;
    const int tid = threadIdx.x;

    /* ---- prologue: reduce q for this (b,h) from qkv partials + bias ---- */
    __shared__ __align__(16) float sq[DHD];
    if (tid < DHD) {
        float v = ba[h * DHD + tid];
        const float* pp = g_qkv_part + (size_t)b * 3 * DM + h * DHD + tid;
        #pragma unroll
        for (int ic = 0; ic < IC_QKV; ic++)
            v += pp[(size_t)ic * BB * 3 * DM];
        sq[tid] = v;
    }
    __syncthreads();
    const float4 qv = ((const float4*)sq)[li];

    const int row0 = split * (KVN / SPLITS) + warp * ROWS_PER_WARP;
    const float4* Kp = (const float4*)(Kc + ((size_t)bh * KVN + row0) * DHD);
    const float4* Vp = (const float4*)(Vc + ((size_t)bh * KVN + row0) * DHD);

    float l = 0.f;
    float4 acc = {0.f, 0.f, 0.f, 0.f};

    for (int it = 0; it < ROWS_PER_WARP / 8; it++) {
        float s[4];
        #pragma unroll
        for (int w = 0; w < 4; w++) {
            const float4 k4 = __ldcs(&Kp[(it * 8 + 2 * w + half) * 16 + li]);
            float p = qv.x * k4.x + qv.y * k4.y + qv.z * k4.z + qv.w * k4.w;
            p += __shfl_xor_sync(0xffffffffu, p, 8);
            p += __shfl_xor_sync(0xffffffffu, p, 4);
            p += __shfl_xor_sync(0xffffffffu, p, 2);
            p += __shfl_xor_sync(0xffffffffu, p, 1);
            s[w] = p;
        }
        #pragma unroll
        for (int w = 0; w < 4; w++) {
            const float e = __expf(s[w]);
            l += e;
            const float4 v4 = __ldcs(&Vp[(it * 8 + 2 * w + half) * 16 + li]);
            acc.x += e * v4.x; acc.y += e * v4.y;
            acc.z += e * v4.z; acc.w += e * v4.w;
        }
    }

    /* merge halves: lane i and i+16 hold same dims for even/odd rows */
    acc.x += __shfl_xor_sync(0xffffffffu, acc.x, 16);
    acc.y += __shfl_xor_sync(0xffffffffu, acc.y, 16);
    acc.z += __shfl_xor_sync(0xffffffffu, acc.z, 16);
    acc.w += __shfl_xor_sync(0xffffffffu, acc.w, 16);
    l += __shfl_xor_sync(0xffffffffu, l, 16);

    /* ---- intra-block reduction of 8 warp-partials -> 1 block-partial ---- */
    __shared__ float sl[WARPS_PER_BLK];
    __shared__ float4 sacc4[WARPS_PER_BLK][16];
    if (half == 0) sacc4[warp][li] = acc;
    if (lane == 0) sl[warp] = l;
    __syncthreads();

    if (tid < DHD) {
        const float* sacc = (const float*)sacc4;
        float num = 0.f;
        #pragma unroll
        for (int w = 0; w < WARPS_PER_BLK; w++) num += sacc[w * DHD + tid];
        g_pacc[((size_t)bh * NPART + split) * DHD + tid] = num;
        if (tid == 0) {
            float den = 0.f;
            #pragma unroll
            for (int w = 0; w < WARPS_PER_BLK; w++) den += sl[w];
            g_pl[bh * NPART + split] = den;
        }
    }
    __syncthreads();

    /* ---- last block per (b,h) performs the combine (threadFenceReduction) ---- */
    __shared__ bool isLast;
    if (tid == 0) {
        __threadfence();
        const unsigned int old = atomicAdd(&g_done[bh], 1u);
        isLast = (old == SPLITS - 1);
    }
    __syncthreads();
    if (!isLast) return;
    __threadfence();

    __shared__ float sred[2];
    float num = 0.f, den = 0.f, kd = 0.f, vd = 0.f, prod = 0.f;
    if (tid < DHD) {
        const float* ap = g_pacc + (size_t)bh * NPART * DHD;
        #pragma unroll
        for (int p = 0; p < NPART; p++) num += ap[p * DHD + tid];
        #pragma unroll
        for (int p = 0; p < NPART; p++) den += g_pl[bh * NPART + p];

        kd = ba[DM + h * DHD + tid];
        vd = ba[2 * DM + h * DHD + tid];
        const float* pk = g_qkv_part + (size_t)b * 3 * DM + DM + h * DHD + tid;
        const float* pv = g_qkv_part + (size_t)b * 3 * DM + 2 * DM + h * DHD + tid;
        #pragma unroll
        for (int ic = 0; ic < IC_QKV; ic++) {
            kd += pk[(size_t)ic * BB * 3 * DM];
            vd += pv[(size_t)ic * BB * 3 * DM];
        }
        prod = sq[tid] * kd;
    }
    /* reduce prod over threads 0..63 (warps 0,1 fully active) */
    prod += __shfl_xor_sync(0xffffffffu, prod, 16);
    prod += __shfl_xor_sync(0xffffffffu, prod, 8);
    prod += __shfl_xor_sync(0xffffffffu, prod, 4);
    prod += __shfl_xor_sync(0xffffffffu, prod, 2);
    prod += __shfl_xor_sync(0xffffffffu, prod, 1);
    if (tid < DHD && lane == 0) sred[warp] = prod;
    __syncthreads();
    const float scur = sred[0] + sred[1];

    if (tid < DHD) {
        const float ec = __expf(scur);   /* same shift (0) as cache scores */
        g_ctx[(size_t)b * DM + h * DHD + tid] =
            (num + ec * vd) / fmaxf(den + ec, 1e-9f);
    }
    if (tid == 0) g_done[bh] = 0;        /* self-reset for next graph replay */
}

/* ============ Batched output projection: weight read ONCE ====================== */
/* grid (8 j-tiles, 32 i-chunks of 32 rows), 128 threads. */
__global__ void proj_part_kernel(const float* __restrict__ w) {
    __shared__ float xs[32 * 33];
    const int tid = threadIdx.x;
    const int j = blockIdx.x * 128 + tid;
    const int i0 = blockIdx.y * 32;

    for (int idx = tid; idx < BB * 32; idx += 128) {
        const int bb = idx >> 5, ii = idx & 31;
        xs[ii * 33 + bb] = g_ctx[bb * DM + i0 + ii];
    }
    __syncthreads();

    float acc[BB];
    #pragma unroll
    for (int bb = 0; bb < BB; bb++) acc[bb] = 0.f;

    const float* wp = w + (size_t)i0 * DM + j;
    #pragma unroll 4
    for (int i = 0; i < 32; i++) {
        const float wv = wp[(size_t)i * DM];
        #pragma unroll
        for (int bb = 0; bb < BB; bb++) acc[bb] += xs[i * 33 + bb] * wv;
    }

    float* op = g_proj_part + (size_t)blockIdx.y * BB * DM + j;
    #pragma unroll
    for (int bb = 0; bb < BB; bb++) op[(size_t)bb * DM] = acc[bb];
}

__global__ void proj_reduce_kernel(const float* __restrict__ bias,
                                   float* __restrict__ out) {
    const int idx = blockIdx.x * 256 + threadIdx.x;   /* 32*1024 elems */
    const int j = idx % DM;
    float s = bias[j];
    #pragma unroll
    for (int ic = 0; ic < IC_PROJ; ic++)
        s += g_proj_part[(size_t)ic * BB * DM + idx];
    out[idx] = s;
}

extern "C" void kernel_launch(void* const* d_in, const int* in_sizes, int n_in,
                              void* d_out, int out_size) {
    const float* hs = (const float*)d_in[0];
    const float* kc = (const float*)d_in[1];
    const float* vc = (const float*)d_in[2];
    const float* wa = (const float*)d_in[3];
    const float* ba = (const float*)d_in[4];
    const float* wp = (const float*)d_in[5];
    const float* bp = (const float*)d_in[6];
    float* out = (float*)d_out;

    qkv_part_kernel<<<dim3(3 * DM / 128, IC_QKV), 128>>>(hs, wa);
    attn_kernel<<<dim3(SPLITS, HH, BB), 256>>>(kc, vc, ba);
    proj_part_kernel<<<dim3(DM / 128, IC_PROJ), 128>>>(wp);
    proj_reduce_kernel<<<BB * DM / 256, 256>>>(bp, out);
}

// round 15
// speedup vs baseline: 1.0011x; 1.0011x over previous
#include <cuda_runtime.h>
#include <math.h>

#define BB 32
#define HH 16
#define KVN 8192
#define DHD 64
#define DM 1024
#define SPLITS 8
#define WARPS_PER_BLK 8
#define ROWS_PER_WARP (KVN / (SPLITS * WARPS_PER_BLK))   /* 128 */
#define NPART SPLITS                                      /* 8 partials per (b,h) */
#define IC_QKV 16                                         /* 64-row i-chunks */
#define IC_PROJ 16                                        /* 64-row i-chunks */

__device__ float g_qkv_part[IC_QKV * BB * 3 * DM];         /* 6.3 MB */
__device__ float g_proj_part[IC_PROJ * BB * DM];           /* 2.1 MB */
__device__ float g_pl[BB * HH * NPART];
__device__ float g_pacc[(size_t)BB * HH * NPART * DHD];    /* 1 MB */
__device__ float g_ctx[BB * DM];

/* ============ Batched QKV GEMV: weight read ONCE, reused across all 32 b ======= */
/* grid (24 j-tiles, 16 i-chunks of 64 rows), 128 threads. */
__global__ void qkv_part_kernel(const float* __restrict__ x,
                                const float* __restrict__ w) {
    __shared__ float xs[64 * 33];
    const int tid = threadIdx.x;
    const int j = blockIdx.x * 128 + tid;
    const int i0 = blockIdx.y * 64;

    for (int idx = tid; idx < BB * 64; idx += 128) {
        const int bb = idx >> 6, ii = idx & 63;
        xs[ii * 33 + bb] = x[bb * DM + i0 + ii];
    }
    __syncthreads();

    float acc[BB];
    #pragma unroll
    for (int bb = 0; bb < BB; bb++) acc[bb] = 0.f;

    const float* wp = w + (size_t)i0 * (3 * DM) + j;
    #pragma unroll 4
    for (int i = 0; i < 64; i++) {
        const float wv = wp[(size_t)i * (3 * DM)];
        #pragma unroll
        for (int bb = 0; bb < BB; bb++) acc[bb] += xs[i * 33 + bb] * wv;
    }

    float* op = g_qkv_part + (size_t)blockIdx.y * BB * 3 * DM + j;
    #pragma unroll
    for (int bb = 0; bb < BB; bb++) op[(size_t)bb * 3 * DM] = acc[bb];
}

/* ---------------- Split-KV attention with q-reduce prologue --------------------- */
/* grid (SPLITS, H, B), 256 thr. No max tracking (scores bounded, fp32-safe;       */
/* softmax shift-invariant). Block-reduces its 8 warps into one partial.           */
__global__ void __launch_bounds__(256) attn_kernel(const float* __restrict__ Kc,
                                                   const float* __restrict__ Vc,
                                                   const float* __restrict__ ba) {
    const int split = blockIdx.x, h = blockIdx.y, b = blockIdx.z;
    const int warp = threadIdx.x >> 5, lane = threadIdx.x & 31;
    const int half = lane >> 4, li = lane & 15;
    const int bh = b * HH + h;
    const int tid = threadIdx.x;

    /* ---- prologue: reduce q for this (b,h) from qkv partials + bias ---- */
    __shared__ __align__(16) float sq[DHD];
    if (tid < DHD) {
        float v = ba[h * DHD + tid];
        const float* pp = g_qkv_part + (size_t)b * 3 * DM + h * DHD + tid;
        #pragma unroll
        for (int ic = 0; ic < IC_QKV; ic++)
            v += pp[(size_t)ic * BB * 3 * DM];
        sq[tid] = v;
    }
    __syncthreads();
    const float4 qv = ((const float4*)sq)[li];

    const int row0 = split * (KVN / SPLITS) + warp * ROWS_PER_WARP;
    const float4* Kp = (const float4*)(Kc + ((size_t)bh * KVN + row0) * DHD);
    const float4* Vp = (const float4*)(Vc + ((size_t)bh * KVN + row0) * DHD);

    float l = 0.f;
    float4 acc = {0.f, 0.f, 0.f, 0.f};

    for (int it = 0; it < ROWS_PER_WARP / 8; it++) {
        float s[4];
        #pragma unroll
        for (int w = 0; w < 4; w++) {
            const float4 k4 = __ldcs(&Kp[(it * 8 + 2 * w + half) * 16 + li]);
            float p = qv.x * k4.x + qv.y * k4.y + qv.z * k4.z + qv.w * k4.w;
            p += __shfl_xor_sync(0xffffffffu, p, 8);
            p += __shfl_xor_sync(0xffffffffu, p, 4);
            p += __shfl_xor_sync(0xffffffffu, p, 2);
            p += __shfl_xor_sync(0xffffffffu, p, 1);
            s[w] = p;
        }
        #pragma unroll
        for (int w = 0; w < 4; w++) {
            const float e = __expf(s[w]);
            l += e;
            const float4 v4 = __ldcs(&Vp[(it * 8 + 2 * w + half) * 16 + li]);
            acc.x += e * v4.x; acc.y += e * v4.y;
            acc.z += e * v4.z; acc.w += e * v4.w;
        }
    }

    /* merge halves: lane i and i+16 hold same dims for even/odd rows */
    acc.x += __shfl_xor_sync(0xffffffffu, acc.x, 16);
    acc.y += __shfl_xor_sync(0xffffffffu, acc.y, 16);
    acc.z += __shfl_xor_sync(0xffffffffu, acc.z, 16);
    acc.w += __shfl_xor_sync(0xffffffffu, acc.w, 16);
    l += __shfl_xor_sync(0xffffffffu, l, 16);

    /* ---- intra-block reduction of 8 warp-partials -> 1 block-partial ---- */
    __shared__ float sl[WARPS_PER_BLK];
    __shared__ float4 sacc4[WARPS_PER_BLK][16];
    if (half == 0) sacc4[warp][li] = acc;
    if (lane == 0) sl[warp] = l;
    __syncthreads();

    if (tid < DHD) {
        const float* sacc = (const float*)sacc4;
        float num = 0.f;
        #pragma unroll
        for (int w = 0; w < WARPS_PER_BLK; w++) num += sacc[w * DHD + tid];
        g_pacc[((size_t)bh * NPART + split) * DHD + tid] = num;
        if (tid == 0) {
            float den = 0.f;
            #pragma unroll
            for (int w = 0; w < WARPS_PER_BLK; w++) den += sl[w];
            g_pl[bh * NPART + split] = den;
        }
    }
}

/* ---------------- Combine 8 partials + fold in current token ------------------- */
/* Reduces current-token q,k,v directly from qkv partials (no qkv_reduce kernel). */
__global__ void combine_kernel(const float* __restrict__ ba) {
    const int bh = blockIdx.x;
    const int b = bh / HH, h = bh % HH;
    const int tid = threadIdx.x;  /* 0..63 = head dim */

    __shared__ float red[64];

    float num = 0.f;
    const float* ap = g_pacc + (size_t)bh * NPART * DHD;
    #pragma unroll
    for (int p = 0; p < NPART; p++) num += ap[p * DHD + tid];

    float den = 0.f;
    #pragma unroll
    for (int p = 0; p < NPART; p++) den += g_pl[bh * NPART + p];

    /* current-token q,k,v from partials + bias */
    float qd = ba[h * DHD + tid];
    float kd = ba[DM + h * DHD + tid];
    float vd = ba[2 * DM + h * DHD + tid];
    const float* pq = g_qkv_part + (size_t)b * 3 * DM +          h * DHD + tid;
    const float* pk = g_qkv_part + (size_t)b * 3 * DM + DM     + h * DHD + tid;
    const float* pv = g_qkv_part + (size_t)b * 3 * DM + 2 * DM + h * DHD + tid;
    #pragma unroll
    for (int ic = 0; ic < IC_QKV; ic++) {
        qd += pq[(size_t)ic * BB * 3 * DM];
        kd += pk[(size_t)ic * BB * 3 * DM];
        vd += pv[(size_t)ic * BB * 3 * DM];
    }

    red[tid] = qd * kd;
    for (int off = 32; off > 0; off >>= 1) {
        __syncthreads();
        if (tid < off) red[tid] += red[tid + off];
    }
    __syncthreads();
    const float ec = __expf(red[0]);   /* current-token score, same shift (0) */

    g_ctx[(size_t)b * DM + h * DHD + tid] =
        (num + ec * vd) / fmaxf(den + ec, 1e-9f);
}

/* ============ Batched output projection: weight read ONCE ====================== */
/* grid (8 j-tiles, 16 i-chunks of 64 rows), 128 threads. */
__global__ void proj_part_kernel(const float* __restrict__ w) {
    __shared__ float xs[64 * 33];
    const int tid = threadIdx.x;
    const int j = blockIdx.x * 128 + tid;
    const int i0 = blockIdx.y * 64;

    for (int idx = tid; idx < BB * 64; idx += 128) {
        const int bb = idx >> 6, ii = idx & 63;
        xs[ii * 33 + bb] = g_ctx[bb * DM + i0 + ii];
    }
    __syncthreads();

    float acc[BB];
    #pragma unroll
    for (int bb = 0; bb < BB; bb++) acc[bb] = 0.f;

    const float* wp = w + (size_t)i0 * DM + j;
    #pragma unroll 4
    for (int i = 0; i < 64; i++) {
        const float wv = wp[(size_t)i * DM];
        #pragma unroll
        for (int bb = 0; bb < BB; bb++) acc[bb] += xs[i * 33 + bb] * wv;
    }

    float* op = g_proj_part + (size_t)blockIdx.y * BB * DM + j;
    #pragma unroll
    for (int bb = 0; bb < BB; bb++) op[(size_t)bb * DM] = acc[bb];
}

__global__ void proj_reduce_kernel(const float* __restrict__ bias,
                                   float* __restrict__ out) {
    const int idx = blockIdx.x * 256 + threadIdx.x;   /* 32*1024 elems */
    const int j = idx % DM;
    float s = bias[j];
    #pragma unroll
    for (int ic = 0; ic < IC_PROJ; ic++)
        s += g_proj_part[(size_t)ic * BB * DM + idx];
    out[idx] = s;
}

extern "C" void kernel_launch(void* const* d_in, const int* in_sizes, int n_in,
                              void* d_out, int out_size) {
    const float* hs = (const float*)d_in[0];
    const float* kc = (const float*)d_in[1];
    const float* vc = (const float*)d_in[2];
    const float* wa = (const float*)d_in[3];
    const float* ba = (const float*)d_in[4];
    const float* wp = (const float*)d_in[5];
    const float* bp = (const float*)d_in[6];
    float* out = (float*)d_out;

    qkv_part_kernel<<<dim3(3 * DM / 128, IC_QKV), 128>>>(hs, wa);
    attn_kernel<<<dim3(SPLITS, HH, BB), 256>>>(kc, vc, ba);
    combine_kernel<<<BB * HH, 64>>>(ba);
    proj_part_kernel<<<dim3(DM / 128, IC_PROJ), 128>>>(wp);
    proj_reduce_kernel<<<BB * DM / 256, 256>>>(bp, out);
}

// round 16
// speedup vs baseline: 1.0224x; 1.0213x over previous
#include <cuda_runtime.h>
#include <math.h>

#define BB 32
#define HH 16
#define KVN 8192
#define DHD 64
#define DM 1024
#define SPLITS 8
#define WARPS_PER_BLK 8
#define ROWS_PER_WARP (KVN / (SPLITS * WARPS_PER_BLK))   /* 128 */
#define NPART SPLITS                                      /* 8 partials per (b,h) */
#define IC_QKV 16                                         /* 64-row i-chunks */
#define IC_PROJ 32                                        /* 32-row i-chunks */

__device__ float g_qkv_part[IC_QKV * BB * 3 * DM];         /* 6.3 MB */
__device__ float g_proj_part[IC_PROJ * BB * DM];           /* 4.2 MB */
__device__ float g_pl[BB * HH * NPART];
__device__ float g_pacc[(size_t)BB * HH * NPART * DHD];    /* 1 MB */
__device__ float g_ctx[BB * DM];

/* ============ Batched QKV GEMV: weight read ONCE, reused across all 32 b ======= */
/* grid (24 j-tiles, 16 i-chunks of 64 rows), 128 threads. */
__global__ void qkv_part_kernel(const float* __restrict__ x,
                                const float* __restrict__ w) {
    __shared__ float xs[64 * 33];
    const int tid = threadIdx.x;
    const int j = blockIdx.x * 128 + tid;
    const int i0 = blockIdx.y * 64;

    for (int idx = tid; idx < BB * 64; idx += 128) {
        const int bb = idx >> 6, ii = idx & 63;
        xs[ii * 33 + bb] = x[bb * DM + i0 + ii];
    }
    __syncthreads();

    float acc[BB];
    #pragma unroll
    for (int bb = 0; bb < BB; bb++) acc[bb] = 0.f;

    const float* wp = w + (size_t)i0 * (3 * DM) + j;
    #pragma unroll 4
    for (int i = 0; i < 64; i++) {
        const float wv = wp[(size_t)i * (3 * DM)];
        #pragma unroll
        for (int bb = 0; bb < BB; bb++) acc[bb] += xs[i * 33 + bb] * wv;
    }

    float* op = g_qkv_part + (size_t)blockIdx.y * BB * 3 * DM + j;
    #pragma unroll
    for (int bb = 0; bb < BB; bb++) op[(size_t)bb * 3 * DM] = acc[bb];
}

/* ---------------- Split-KV attention with q-reduce prologue --------------------- */
/* grid (SPLITS, H, B), 256 thr. No max tracking (scores bounded, fp32-safe;       */
/* softmax shift-invariant). Block-reduces its 8 warps into one partial.           */
__global__ void __launch_bounds__(256) attn_kernel(const float* __restrict__ Kc,
                                                   const float* __restrict__ Vc,
                                                   const float* __restrict__ ba) {
    const int split = blockIdx.x, h = blockIdx.y, b = blockIdx.z;
    const int warp = threadIdx.x >> 5, lane = threadIdx.x & 31;
    const int half = lane >> 4, li = lane & 15;
    const int bh = b * HH + h;
    const int tid = threadIdx.x;

    /* ---- prologue: reduce q for this (b,h) from qkv partials + bias ---- */
    __shared__ __align__(16) float sq[DHD];
    if (tid < DHD) {
        float v = ba[h * DHD + tid];
        const float* pp = g_qkv_part + (size_t)b * 3 * DM + h * DHD + tid;
        #pragma unroll
        for (int ic = 0; ic < IC_QKV; ic++)
            v += pp[(size_t)ic * BB * 3 * DM];
        sq[tid] = v;
    }
    __syncthreads();
    const float4 qv = ((const float4*)sq)[li];

    const int row0 = split * (KVN / SPLITS) + warp * ROWS_PER_WARP;
    const float4* Kp = (const float4*)(Kc + ((size_t)bh * KVN + row0) * DHD);
    const float4* Vp = (const float4*)(Vc + ((size_t)bh * KVN + row0) * DHD);

    float l = 0.f;
    float4 acc = {0.f, 0.f, 0.f, 0.f};

    for (int it = 0; it < ROWS_PER_WARP / 8; it++) {
        float s[4];
        #pragma unroll
        for (int w = 0; w < 4; w++) {
            const float4 k4 = __ldcs(&Kp[(it * 8 + 2 * w + half) * 16 + li]);
            float p = qv.x * k4.x + qv.y * k4.y + qv.z * k4.z + qv.w * k4.w;
            p += __shfl_xor_sync(0xffffffffu, p, 8);
            p += __shfl_xor_sync(0xffffffffu, p, 4);
            p += __shfl_xor_sync(0xffffffffu, p, 2);
            p += __shfl_xor_sync(0xffffffffu, p, 1);
            s[w] = p;
        }
        #pragma unroll
        for (int w = 0; w < 4; w++) {
            const float e = __expf(s[w]);
            l += e;
            const float4 v4 = __ldcs(&Vp[(it * 8 + 2 * w + half) * 16 + li]);
            acc.x += e * v4.x; acc.y += e * v4.y;
            acc.z += e * v4.z; acc.w += e * v4.w;
        }
    }

    /* merge halves: lane i and i+16 hold same dims for even/odd rows */
    acc.x += __shfl_xor_sync(0xffffffffu, acc.x, 16);
    acc.y += __shfl_xor_sync(0xffffffffu, acc.y, 16);
    acc.z += __shfl_xor_sync(0xffffffffu, acc.z, 16);
    acc.w += __shfl_xor_sync(0xffffffffu, acc.w, 16);
    l += __shfl_xor_sync(0xffffffffu, l, 16);

    /* ---- intra-block reduction of 8 warp-partials -> 1 block-partial ---- */
    __shared__ float sl[WARPS_PER_BLK];
    __shared__ float4 sacc4[WARPS_PER_BLK][16];
    if (half == 0) sacc4[warp][li] = acc;
    if (lane == 0) sl[warp] = l;
    __syncthreads();

    if (tid < DHD) {
        const float* sacc = (const float*)sacc4;
        float num = 0.f;
        #pragma unroll
        for (int w = 0; w < WARPS_PER_BLK; w++) num += sacc[w * DHD + tid];
        g_pacc[((size_t)bh * NPART + split) * DHD + tid] = num;
        if (tid == 0) {
            float den = 0.f;
            #pragma unroll
            for (int w = 0; w < WARPS_PER_BLK; w++) den += sl[w];
            g_pl[bh * NPART + split] = den;
        }
    }
}

/* ---------------- Combine 8 partials + fold in current token ------------------- */
/* Reduces current-token q,k,v directly from qkv partials (no qkv_reduce kernel). */
__global__ void combine_kernel(const float* __restrict__ ba) {
    const int bh = blockIdx.x;
    const int b = bh / HH, h = bh % HH;
    const int tid = threadIdx.x;  /* 0..63 = head dim */

    __shared__ float red[64];

    float num = 0.f;
    const float* ap = g_pacc + (size_t)bh * NPART * DHD;
    #pragma unroll
    for (int p = 0; p < NPART; p++) num += ap[p * DHD + tid];

    float den = 0.f;
    #pragma unroll
    for (int p = 0; p < NPART; p++) den += g_pl[bh * NPART + p];

    /* current-token q,k,v from partials + bias */
    float qd = ba[h * DHD + tid];
    float kd = ba[DM + h * DHD + tid];
    float vd = ba[2 * DM + h * DHD + tid];
    const float* pq = g_qkv_part + (size_t)b * 3 * DM +          h * DHD + tid;
    const float* pk = g_qkv_part + (size_t)b * 3 * DM + DM     + h * DHD + tid;
    const float* pv = g_qkv_part + (size_t)b * 3 * DM + 2 * DM + h * DHD + tid;
    #pragma unroll
    for (int ic = 0; ic < IC_QKV; ic++) {
        qd += pq[(size_t)ic * BB * 3 * DM];
        kd += pk[(size_t)ic * BB * 3 * DM];
        vd += pv[(size_t)ic * BB * 3 * DM];
    }

    red[tid] = qd * kd;
    for (int off = 32; off > 0; off >>= 1) {
        __syncthreads();
        if (tid < off) red[tid] += red[tid + off];
    }
    __syncthreads();
    const float ec = __expf(red[0]);   /* current-token score, same shift (0) */

    g_ctx[(size_t)b * DM + h * DHD + tid] =
        (num + ec * vd) / fmaxf(den + ec, 1e-9f);
}

/* ============ Batched output projection: weight read ONCE ====================== */
/* grid (8 j-tiles, 32 i-chunks of 32 rows), 128 threads. */
__global__ void proj_part_kernel(const float* __restrict__ w) {
    __shared__ float xs[32 * 33];
    const int tid = threadIdx.x;
    const int j = blockIdx.x * 128 + tid;
    const int i0 = blockIdx.y * 32;

    for (int idx = tid; idx < BB * 32; idx += 128) {
        const int bb = idx >> 5, ii = idx & 31;
        xs[ii * 33 + bb] = g_ctx[bb * DM + i0 + ii];
    }
    __syncthreads();

    float acc[BB];
    #pragma unroll
    for (int bb = 0; bb < BB; bb++) acc[bb] = 0.f;

    const float* wp = w + (size_t)i0 * DM + j;
    #pragma unroll 4
    for (int i = 0; i < 32; i++) {
        const float wv = wp[(size_t)i * DM];
        #pragma unroll
        for (int bb = 0; bb < BB; bb++) acc[bb] += xs[i * 33 + bb] * wv;
    }

    float* op = g_proj_part + (size_t)blockIdx.y * BB * DM + j;
    #pragma unroll
    for (int bb = 0; bb < BB; bb++) op[(size_t)bb * DM] = acc[bb];
}

__global__ void proj_reduce_kernel(const float* __restrict__ bias,
                                   float* __restrict__ out) {
    const int idx = blockIdx.x * 256 + threadIdx.x;   /* 32*1024 elems */
    const int j = idx % DM;
    float s = bias[j];
    #pragma unroll
    for (int ic = 0; ic < IC_PROJ; ic++)
        s += g_proj_part[(size_t)ic * BB * DM + idx];
    out[idx] = s;
}

extern "C" void kernel_launch(void* const* d_in, const int* in_sizes, int n_in,
                              void* d_out, int out_size) {
    const float* hs = (const float*)d_in[0];
    const float* kc = (const float*)d_in[1];
    const float* vc = (const float*)d_in[2];
    const float* wa = (const float*)d_in[3];
    const float* ba = (const float*)d_in[4];
    const float* wp = (const float*)d_in[5];
    const float* bp = (const float*)d_in[6];
    float* out = (float*)d_out;

    qkv_part_kernel<<<dim3(3 * DM / 128, IC_QKV), 128>>>(hs, wa);
    attn_kernel<<<dim3(SPLITS, HH, BB), 256>>>(kc, vc, ba);
    combine_kernel<<<BB * HH, 64>>>(ba);
    proj_part_kernel<<<dim3(DM / 128, IC_PROJ), 128>>>(wp);
    proj_reduce_kernel<<<BB * DM / 256, 256>>>(bp, out);
}

// round 17
// speedup vs baseline: 1.0483x; 1.0254x over previous
#include <cuda_runtime.h>
#include <math.h>

#define BB 32
#define HH 16
#define KVN 8192
#define DHD 64
#define DM 1024
#define SPLITS 8
#define WARPS_PER_BLK 8
#define ROWS_PER_WARP (KVN / (SPLITS * WARPS_PER_BLK))   /* 128 */
#define NPART SPLITS                                      /* 8 partials per (b,h) */
#define IC_QKV 16                                         /* 64-row i-chunks */
#define IC_PROJ 32                                        /* 32-row i-chunks */
#define BSPLIT 2                                          /* batch split for GEMVs */
#define BBH (BB / BSPLIT)                                 /* 16 batches per block */

__device__ float g_qkv[BB * 3 * DM];                       /* [B][3D] */
__device__ float g_qkv_part[IC_QKV * BB * 3 * DM];         /* 6.3 MB */
__device__ float g_proj_part[IC_PROJ * BB * DM];           /* 4.2 MB */
__device__ float g_pl[BB * HH * NPART];
__device__ float g_pacc[(size_t)BB * HH * NPART * DHD];    /* 1 MB */
__device__ float g_ctx[BB * DM];

/* ============ Batched QKV GEMV: grid (24 j, 16 i-chunks, 2 b-halves), 128 thr == */
__global__ void qkv_part_kernel(const float* __restrict__ x,
                                const float* __restrict__ w) {
    __shared__ float xs[64 * 17];
    const int tid = threadIdx.x;
    const int j = blockIdx.x * 128 + tid;
    const int i0 = blockIdx.y * 64;
    const int b0 = blockIdx.z * BBH;

    for (int idx = tid; idx < BBH * 64; idx += 128) {
        const int bb = idx >> 6, ii = idx & 63;
        xs[ii * 17 + bb] = x[(b0 + bb) * DM + i0 + ii];
    }
    __syncthreads();

    float acc[BBH];
    #pragma unroll
    for (int bb = 0; bb < BBH; bb++) acc[bb] = 0.f;

    const float* wp = w + (size_t)i0 * (3 * DM) + j;
    #pragma unroll 4
    for (int i = 0; i < 64; i++) {
        const float wv = wp[(size_t)i * (3 * DM)];
        #pragma unroll
        for (int bb = 0; bb < BBH; bb++) acc[bb] += xs[i * 17 + bb] * wv;
    }

    float* op = g_qkv_part + (size_t)blockIdx.y * BB * 3 * DM + (size_t)b0 * 3 * DM + j;
    #pragma unroll
    for (int bb = 0; bb < BBH; bb++) op[(size_t)bb * 3 * DM] = acc[bb];
}

__global__ void qkv_reduce_kernel(const float* __restrict__ bias) {
    const int idx = blockIdx.x * 256 + threadIdx.x;   /* 32*3072 elems */
    const int j = idx % (3 * DM);
    float s = bias[j];
    #pragma unroll
    for (int ic = 0; ic < IC_QKV; ic++)
        s += g_qkv_part[(size_t)ic * BB * 3 * DM + idx];
    g_qkv[idx] = s;
}

/* ---------------- Split-KV attention (float4, no max tracking) ------------------ */
__global__ void __launch_bounds__(256) attn_kernel(const float* __restrict__ Kc,
                                                   const float* __restrict__ Vc) {
    const int split = blockIdx.x, h = blockIdx.y, b = blockIdx.z;
    const int warp = threadIdx.x >> 5, lane = threadIdx.x & 31;
    const int half = lane >> 4, li = lane & 15;
    const int bh = b * HH + h;

    const float4 qv = ((const float4*)(g_qkv + (size_t)b * 3 * DM + h * DHD))[li];

    const int row0 = split * (KVN / SPLITS) + warp * ROWS_PER_WARP;
    const float4* Kp = (const float4*)(Kc + ((size_t)bh * KVN + row0) * DHD);
    const float4* Vp = (const float4*)(Vc + ((size_t)bh * KVN + row0) * DHD);

    float l = 0.f;
    float4 acc = {0.f, 0.f, 0.f, 0.f};

    for (int it = 0; it < ROWS_PER_WARP / 8; it++) {
        float s[4];
        #pragma unroll
        for (int w = 0; w < 4; w++) {
            const float4 k4 = __ldcs(&Kp[(it * 8 + 2 * w + half) * 16 + li]);
            float p = qv.x * k4.x + qv.y * k4.y + qv.z * k4.z + qv.w * k4.w;
            p += __shfl_xor_sync(0xffffffffu, p, 8);
            p += __shfl_xor_sync(0xffffffffu, p, 4);
            p += __shfl_xor_sync(0xffffffffu, p, 2);
            p += __shfl_xor_sync(0xffffffffu, p, 1);
            s[w] = p;
        }
        #pragma unroll
        for (int w = 0; w < 4; w++) {
            const float e = __expf(s[w]);
            l += e;
            const float4 v4 = __ldcs(&Vp[(it * 8 + 2 * w + half) * 16 + li]);
            acc.x += e * v4.x; acc.y += e * v4.y;
            acc.z += e * v4.z; acc.w += e * v4.w;
        }
    }

    /* merge halves: lane i and i+16 hold same dims for even/odd rows */
    acc.x += __shfl_xor_sync(0xffffffffu, acc.x, 16);
    acc.y += __shfl_xor_sync(0xffffffffu, acc.y, 16);
    acc.z += __shfl_xor_sync(0xffffffffu, acc.z, 16);
    acc.w += __shfl_xor_sync(0xffffffffu, acc.w, 16);
    l += __shfl_xor_sync(0xffffffffu, l, 16);

    /* ---- intra-block reduction of 8 warp-partials -> 1 block-partial ---- */
    __shared__ float sl[WARPS_PER_BLK];
    __shared__ float4 sacc4[WARPS_PER_BLK][16];
    if (half == 0) sacc4[warp][li] = acc;
    if (lane == 0) sl[warp] = l;
    __syncthreads();

    const int tid = threadIdx.x;
    if (tid < DHD) {
        const float* sacc = (const float*)sacc4;
        float num = 0.f;
        #pragma unroll
        for (int w = 0; w < WARPS_PER_BLK; w++) num += sacc[w * DHD + tid];
        g_pacc[((size_t)bh * NPART + split) * DHD + tid] = num;
        if (tid == 0) {
            float den = 0.f;
            #pragma unroll
            for (int w = 0; w < WARPS_PER_BLK; w++) den += sl[w];
            g_pl[bh * NPART + split] = den;
        }
    }
}

/* ---------------- Combine 8 partials + fold in current token ------------------- */
__global__ void combine_kernel() {
    const int bh = blockIdx.x;
    const int b = bh / HH, h = bh % HH;
    const int tid = threadIdx.x;  /* 0..63 = head dim */

    __shared__ float red[64];

    float num = 0.f;
    const float* ap = g_pacc + (size_t)bh * NPART * DHD;
    #pragma unroll
    for (int p = 0; p < NPART; p++) num += ap[p * DHD + tid];

    float den = 0.f;
    #pragma unroll
    for (int p = 0; p < NPART; p++) den += g_pl[bh * NPART + p];

    const float qd = g_qkv[(size_t)b * 3 * DM +            h * DHD + tid];
    const float kd = g_qkv[(size_t)b * 3 * DM + DM      +  h * DHD + tid];
    const float vd = g_qkv[(size_t)b * 3 * DM + 2 * DM  +  h * DHD + tid];

    red[tid] = qd * kd;
    for (int off = 32; off > 0; off >>= 1) {
        __syncthreads();
        if (tid < off) red[tid] += red[tid + off];
    }
    __syncthreads();
    const float ec = __expf(red[0]);   /* current-token score, same shift (0) */

    g_ctx[(size_t)b * DM + h * DHD + tid] =
        (num + ec * vd) / fmaxf(den + ec, 1e-9f);
}

/* ============ Batched output projection: grid (8 j, 32 i-chunks, 2 b-halves) === */
__global__ void proj_part_kernel(const float* __restrict__ w) {
    __shared__ float xs[32 * 17];
    const int tid = threadIdx.x;
    const int j = blockIdx.x * 128 + tid;
    const int i0 = blockIdx.y * 32;
    const int b0 = blockIdx.z * BBH;

    for (int idx = tid; idx < BBH * 32; idx += 128) {
        const int bb = idx >> 5, ii = idx & 31;
        xs[ii * 17 + bb] = g_ctx[(b0 + bb) * DM + i0 + ii];
    }
    __syncthreads();

    float acc[BBH];
    #pragma unroll
    for (int bb = 0; bb < BBH; bb++) acc[bb] = 0.f;

    const float* wp = w + (size_t)i0 * DM + j;
    #pragma unroll 4
    for (int i = 0; i < 32; i++) {
        const float wv = wp[(size_t)i * DM];
        #pragma unroll
        for (int bb = 0; bb < BBH; bb++) acc[bb] += xs[i * 17 + bb] * wv;
    }

    float* op = g_proj_part + (size_t)blockIdx.y * BB * DM + (size_t)b0 * DM + j;
    #pragma unroll
    for (int bb = 0; bb < BBH; bb++) op[(size_t)bb * DM] = acc[bb];
}

__global__ void proj_reduce_kernel(const float* __restrict__ bias,
                                   float* __restrict__ out) {
    const int idx = blockIdx.x * 256 + threadIdx.x;   /* 32*1024 elems */
    const int j = idx % DM;
    float s = bias[j];
    #pragma unroll
    for (int ic = 0; ic < IC_PROJ; ic++)
        s += g_proj_part[(size_t)ic * BB * DM + idx];
    out[idx] = s;
}

extern "C" void kernel_launch(void* const* d_in, const int* in_sizes, int n_in,
                              void* d_out, int out_size) {
    const float* hs = (const float*)d_in[0];
    const float* kc = (const float*)d_in[1];
    const float* vc = (const float*)d_in[2];
    const float* wa = (const float*)d_in[3];
    const float* ba = (const float*)d_in[4];
    const float* wp = (const float*)d_in[5];
    const float* bp = (const float*)d_in[6];
    float* out = (float*)d_out;

    qkv_part_kernel<<<dim3(3 * DM / 128, IC_QKV, BSPLIT), 128>>>(hs, wa);
    qkv_reduce_kernel<<<BB * 3 * DM / 256, 256>>>(ba);
    attn_kernel<<<dim3(SPLITS, HH, BB), 256>>>(kc, vc);
    combine_kernel<<<BB * HH, 64>>>();
    proj_part_kernel<<<dim3(DM / 128, IC_PROJ, BSPLIT), 128>>>(wp);
    proj_reduce_kernel<<<BB * DM / 256, 256>>>(bp, out);
}